// round 4
// baseline (speedup 1.0000x reference)
#include <cuda_runtime.h>
#include <cuda_bf16.h>
#include <cstdint>
#include <math.h>

using bf16 = __nv_bfloat16;
#define DINLINE __device__ __forceinline__

// ---------------- problem dims ----------------
#define D_IN 1024
#define HID  512
#define WAYS 64
#define S_N  1024
#define Q_N  4096

// ---------------- scratch (device globals; no allocation allowed) ----------------
__device__ __align__(256) bf16  g_sxb[S_N * D_IN];
__device__ __align__(256) bf16  g_qxb[Q_N * D_IN];
__device__ __align__(256) bf16  g_W1t[HID * D_IN];   // [n][k] = W1[k][n]
__device__ __align__(256) bf16  g_W2t[HID * HID];
__device__ __align__(256) bf16  g_R1tT[HID * HID];   // R1w[:512] transposed
__device__ __align__(256) bf16  g_R1bT[HID * HID];   // R1w[512:] transposed
__device__ __align__(256) bf16  g_R2t[HID * HID];
__device__ __align__(256) bf16  g_sf1[S_N * HID];
__device__ __align__(256) float g_sf [S_N * HID];
__device__ __align__(256) bf16  g_qf1[Q_N * HID];
__device__ __align__(256) bf16  g_qf [Q_N * HID];
__device__ __align__(256) bf16  g_protosb[WAYS * HID];
__device__ __align__(256) float g_qp [Q_N * HID];
__device__ __align__(256) float g_pp [WAYS * HID];

// ---------------- PTX helpers ----------------
DINLINE uint32_t smem_u32(const void* p) { return (uint32_t)__cvta_generic_to_shared(p); }

DINLINE void cp16(uint32_t saddr, const void* g) {
    asm volatile("cp.async.cg.shared.global [%0], [%1], 16;\n" :: "r"(saddr), "l"(g));
}
DINLINE void cp_commit() { asm volatile("cp.async.commit_group;\n"); }
DINLINE void cp_wait0()  { asm volatile("cp.async.wait_group 0;\n"); }
DINLINE void cp_wait1()  { asm volatile("cp.async.wait_group 1;\n"); }

DINLINE void ldmx4(uint32_t& r0, uint32_t& r1, uint32_t& r2, uint32_t& r3, uint32_t a) {
    asm volatile("ldmatrix.sync.aligned.m8n8.x4.shared.b16 {%0,%1,%2,%3}, [%4];\n"
                 : "=r"(r0), "=r"(r1), "=r"(r2), "=r"(r3) : "r"(a));
}
DINLINE void mma16816(float* c, uint32_t a0, uint32_t a1, uint32_t a2, uint32_t a3,
                      uint32_t b0, uint32_t b1) {
    asm volatile("mma.sync.aligned.m16n8k16.row.col.f32.bf16.bf16.f32 "
                 "{%0,%1,%2,%3}, {%4,%5,%6,%7}, {%8,%9}, {%0,%1,%2,%3};\n"
                 : "+f"(c[0]), "+f"(c[1]), "+f"(c[2]), "+f"(c[3])
                 : "r"(a0), "r"(a1), "r"(a2), "r"(a3), "r"(b0), "r"(b1));
}

// ---------------- small utility kernels ----------------
__global__ void convert_bf16_k(const float* __restrict__ in, bf16* __restrict__ out, int n) {
    int i = (blockIdx.x * blockDim.x + threadIdx.x) * 4;
    if (i < n) {
        float4 v = *(const float4*)(in + i);
        __nv_bfloat162 lo = __floats2bfloat162_rn(v.x, v.y);
        __nv_bfloat162 hi = __floats2bfloat162_rn(v.z, v.w);
        uint2 u;
        u.x = *reinterpret_cast<uint32_t*>(&lo);
        u.y = *reinterpret_cast<uint32_t*>(&hi);
        *(uint2*)(out + i) = u;
    }
}

// out[n*K + k] = bf16(in[(k + koff)*N + n]), in is [K_total][N=512] f32
__global__ void transpose_convert_k(const float* __restrict__ in, bf16* __restrict__ out,
                                    int K, int koff) {
    int idx = blockIdx.x * blockDim.x + threadIdx.x;
    if (idx < K * HID) {
        int n = idx / K;
        int k = idx - n * K;
        out[idx] = __float2bfloat16(in[(size_t)(k + koff) * HID + n]);
    }
}

// class prototypes: one block per class, 512 threads (one per hidden dim)
__global__ void protos_k(const float* __restrict__ sf, const int* __restrict__ y,
                         bf16* __restrict__ pb) {
    __shared__ int ys[S_N];
    int w = blockIdx.x;
    for (int i = threadIdx.x; i < S_N; i += blockDim.x) ys[i] = y[i];
    __syncthreads();
    int h = threadIdx.x;
    float acc = 0.f;
    int cnt = 0;
    for (int s = 0; s < S_N; s++) {
        if (ys[s] == w) { acc += sf[(size_t)s * HID + h]; cnt++; }
    }
    float c = (float)(cnt > 0 ? cnt : 1);
    pb[(size_t)w * HID + h] = __float2bfloat16(acc / c);
}

// ---------------- generic bf16 TN GEMM: C[M,512] = act(A[M,K] @ Bt[512,K]^T + bias) ----------------
// A row-major k-contiguous, Bt row-major k-contiguous. BM=BN=128, BK=64, 256 threads.
template <bool BIAS, bool RELU, bool F32OUT>
__global__ void __launch_bounds__(256) gemm_k(
    const bf16* __restrict__ A, const bf16* __restrict__ Bt,
    const float* __restrict__ bias,
    float* __restrict__ outF, bf16* __restrict__ outB,
    int M, int K)
{
    extern __shared__ bf16 sm[];
    bf16* As = sm;                 // [2][128][72]
    bf16* Bs = sm + 2 * 128 * 72;  // [2][128][72]
    const int tid = threadIdx.x;
    const int m0 = blockIdx.y * 128, n0 = blockIdx.x * 128;
    const int wid = tid >> 5, lane = tid & 31;
    const int wm = wid >> 2, wn = wid & 3;
    const int grp = lane >> 2, tig = lane & 3;
    const uint32_t as_b = smem_u32(As), bs_b = smem_u32(Bs);

    auto load_tile = [&](int st, int kt) {
#pragma unroll
        for (int i = tid; i < 2048; i += 256) {
            int r  = (i & 1023) >> 3;
            int ks = (i & 7) << 3;
            if (i < 1024) {
                int ar = m0 + r; if (ar >= M) ar = M - 1;
                cp16(as_b + (uint32_t)(st * 9216 + r * 72 + ks) * 2,
                     A + (size_t)ar * K + kt * 64 + ks);
            } else {
                cp16(bs_b + (uint32_t)(st * 9216 + r * 72 + ks) * 2,
                     Bt + (size_t)(n0 + r) * K + kt * 64 + ks);
            }
        }
        cp_commit();
    };

    float c[4][4][4];
#pragma unroll
    for (int a = 0; a < 4; a++)
#pragma unroll
        for (int b = 0; b < 4; b++)
#pragma unroll
            for (int e = 0; e < 4; e++) c[a][b][e] = 0.f;

    const int KT = K >> 6;
    load_tile(0, 0);
    for (int kt = 0; kt < KT; kt++) {
        if (kt + 1 < KT) { load_tile((kt + 1) & 1, kt + 1); cp_wait1(); }
        else             { cp_wait0(); }
        __syncthreads();
        int st = kt & 1;
#pragma unroll
        for (int k16 = 0; k16 < 4; k16++) {
            uint32_t afr[4][4];
            uint32_t abase = as_b + (uint32_t)((st * 9216 + (wm * 64 + (lane & 15)) * 72
                                    + k16 * 16 + ((lane >> 4) << 3)) * 2);
#pragma unroll
            for (int ms = 0; ms < 4; ms++)
                ldmx4(afr[ms][0], afr[ms][1], afr[ms][2], afr[ms][3],
                      abase + (uint32_t)(ms * 16 * 72 * 2));
            uint32_t bfr[4][2];
#pragma unroll
            for (int ns = 0; ns < 4; ns++) {
                const bf16* p = Bs + st * 9216 + (wn * 32 + ns * 8 + grp) * 72
                                + k16 * 16 + 2 * tig;
                bfr[ns][0] = *(const uint32_t*)p;
                bfr[ns][1] = *(const uint32_t*)(p + 8);
            }
#pragma unroll
            for (int ms = 0; ms < 4; ms++)
#pragma unroll
                for (int ns = 0; ns < 4; ns++)
                    mma16816(c[ms][ns], afr[ms][0], afr[ms][1], afr[ms][2], afr[ms][3],
                             bfr[ns][0], bfr[ns][1]);
        }
        __syncthreads();
    }

#pragma unroll
    for (int ms = 0; ms < 4; ms++) {
#pragma unroll
        for (int i = 0; i < 4; i++) {
            int row = m0 + wm * 64 + ms * 16 + grp + ((i >> 1) << 3);
            if (row < M) {
#pragma unroll
                for (int ns = 0; ns < 4; ns++) {
                    int col = n0 + wn * 32 + ns * 8 + tig * 2 + (i & 1);
                    float v = c[ms][ns][i];
                    if (BIAS) v += bias[col];
                    if (RELU) v = fmaxf(v, 0.f);
                    if (F32OUT) outF[(size_t)row * HID + col] = v;
                    else        outB[(size_t)row * HID + col] = __float2bfloat16(v);
                }
            }
        }
    }
}

// ---------------- fused relation kernel ----------------
// out[q*64+w] = sigmoid( sum_n relu( sum_k relu(qp[q,k]+pp[w,k]) * R2w[k,n] + R2b[n] ) * R3w[n] + R3b )
// Each CTA: 128 rows (2 q x 64 w), full N=512, K=512. A built once in SMEM, 4 N-passes.
__global__ void __launch_bounds__(256) relation_k(
    const float* __restrict__ qp, const float* __restrict__ pp,
    const bf16* __restrict__ Bt,  // R2w transposed [n][k]
    const float* __restrict__ R2b, const float* __restrict__ R3w,
    const float* __restrict__ R3b, float* __restrict__ out)
{
    extern __shared__ bf16 sm[];
    bf16* As = sm;                           // [128][520]
    bf16* Bs = sm + 128 * 520;               // [2][128][72]
    float* red = (float*)(sm + 128 * 520 + 2 * 128 * 72);  // [128][4]
    const int tid = threadIdx.x;
    const int wid = tid >> 5, lane = tid & 31;
    const int wm = wid >> 2, wn = wid & 3;
    const int grp = lane >> 2, tig = lane & 3;
    const int q0 = blockIdx.x * 2;
    const uint32_t as_b = smem_u32(As), bs_b = smem_u32(Bs);

    // Build A tile: As[r][k] = bf16(relu(qp[q0 + r/64][k] + pp[r%64][k]))
    for (int i = tid; i < 128 * 128; i += 256) {
        int r = i >> 7, k = (i & 127) << 2;
        int q = q0 + (r >> 6), w = r & 63;
        float4 a = *(const float4*)(qp + (size_t)q * HID + k);
        float4 b = *(const float4*)(pp + (size_t)w * HID + k);
        __nv_bfloat162 lo = __floats2bfloat162_rn(fmaxf(a.x + b.x, 0.f), fmaxf(a.y + b.y, 0.f));
        __nv_bfloat162 hi = __floats2bfloat162_rn(fmaxf(a.z + b.z, 0.f), fmaxf(a.w + b.w, 0.f));
        uint2 u;
        u.x = *reinterpret_cast<uint32_t*>(&lo);
        u.y = *reinterpret_cast<uint32_t*>(&hi);
        *(uint2*)(As + r * 520 + k) = u;
    }
    __syncthreads();

    float rp[8];
#pragma unroll
    for (int j = 0; j < 8; j++) rp[j] = 0.f;

    for (int npass = 0; npass < 4; npass++) {
        const int n0 = npass * 128;
        float c[4][4][4];
#pragma unroll
        for (int a = 0; a < 4; a++)
#pragma unroll
            for (int b = 0; b < 4; b++)
#pragma unroll
                for (int e = 0; e < 4; e++) c[a][b][e] = 0.f;

        auto loadB = [&](int st, int kt) {
#pragma unroll
            for (int i = tid; i < 1024; i += 256) {
                int r = i >> 3, ks = (i & 7) << 3;
                cp16(bs_b + (uint32_t)(st * 9216 + r * 72 + ks) * 2,
                     Bt + (size_t)(n0 + r) * HID + kt * 64 + ks);
            }
            cp_commit();
        };

        loadB(0, 0);
        for (int kt = 0; kt < 8; kt++) {
            if (kt < 7) { loadB((kt + 1) & 1, kt + 1); cp_wait1(); }
            else        { cp_wait0(); }
            __syncthreads();
            int st = kt & 1;
#pragma unroll
            for (int k16 = 0; k16 < 4; k16++) {
                uint32_t afr[4][4];
                uint32_t abase = as_b + (uint32_t)(((wm * 64 + (lane & 15)) * 520
                                        + kt * 64 + k16 * 16 + ((lane >> 4) << 3)) * 2);
#pragma unroll
                for (int ms = 0; ms < 4; ms++)
                    ldmx4(afr[ms][0], afr[ms][1], afr[ms][2], afr[ms][3],
                          abase + (uint32_t)(ms * 16 * 520 * 2));
                uint32_t bfr[4][2];
#pragma unroll
                for (int ns = 0; ns < 4; ns++) {
                    const bf16* p = Bs + st * 9216 + (wn * 32 + ns * 8 + grp) * 72
                                    + k16 * 16 + 2 * tig;
                    bfr[ns][0] = *(const uint32_t*)p;
                    bfr[ns][1] = *(const uint32_t*)(p + 8);
                }
#pragma unroll
                for (int ms = 0; ms < 4; ms++)
#pragma unroll
                    for (int ns = 0; ns < 4; ns++)
                        mma16816(c[ms][ns], afr[ms][0], afr[ms][1], afr[ms][2], afr[ms][3],
                                 bfr[ns][0], bfr[ns][1]);
            }
            __syncthreads();
        }

        // epilogue: relu(+R2b) * R3w, reduce over this pass's 128 columns
#pragma unroll
        for (int ns = 0; ns < 4; ns++) {
            int colbase = n0 + wn * 32 + ns * 8 + tig * 2;
            float bb0 = R2b[colbase], bb1 = R2b[colbase + 1];
            float w0 = R3w[colbase],  w1 = R3w[colbase + 1];
#pragma unroll
            for (int ms = 0; ms < 4; ms++) {
                rp[ms * 2 + 0] += fmaxf(c[ms][ns][0] + bb0, 0.f) * w0
                                + fmaxf(c[ms][ns][1] + bb1, 0.f) * w1;
                rp[ms * 2 + 1] += fmaxf(c[ms][ns][2] + bb0, 0.f) * w0
                                + fmaxf(c[ms][ns][3] + bb1, 0.f) * w1;
            }
        }
    }

    // reduce across tig (4 threads per row) then across 4 n-warps via smem
#pragma unroll
    for (int j = 0; j < 8; j++) {
        rp[j] += __shfl_xor_sync(0xffffffffu, rp[j], 1);
        rp[j] += __shfl_xor_sync(0xffffffffu, rp[j], 2);
    }
    if (tig == 0) {
#pragma unroll
        for (int j = 0; j < 8; j++) {
            int row = wm * 64 + (j >> 1) * 16 + grp + (j & 1) * 8;
            red[row * 4 + wn] = rp[j];
        }
    }
    __syncthreads();
    if (tid < 128) {
        float s = red[tid * 4 + 0] + red[tid * 4 + 1] + red[tid * 4 + 2] + red[tid * 4 + 3]
                + R3b[0];
        out[(size_t)blockIdx.x * 128 + tid] = 1.f / (1.f + expf(-s));
    }
}

// ---------------- host launcher ----------------
extern "C" void kernel_launch(void* const* d_in, const int* in_sizes, int n_in,
                              void* d_out, int out_size)
{
    (void)in_sizes; (void)n_in; (void)out_size;
    const float* support_x = (const float*)d_in[0];
    const int*   support_y = (const int*)d_in[1];
    const float* query_x   = (const float*)d_in[2];
    const float* W1  = (const float*)d_in[3];
    const float* b1  = (const float*)d_in[4];
    const float* W2  = (const float*)d_in[5];
    const float* b2  = (const float*)d_in[6];
    const float* R1w = (const float*)d_in[7];
    const float* R1b = (const float*)d_in[8];
    const float* R2w = (const float*)d_in[9];
    const float* R2b = (const float*)d_in[10];
    const float* R3w = (const float*)d_in[11];
    const float* R3b = (const float*)d_in[12];
    float* out = (float*)d_out;

    bf16 *sxb, *qxb, *W1t, *W2t, *R1tT, *R1bT, *R2t, *sf1, *qf1, *qf, *protosb;
    float *sf, *qp, *pp;
    cudaGetSymbolAddress((void**)&sxb, g_sxb);
    cudaGetSymbolAddress((void**)&qxb, g_qxb);
    cudaGetSymbolAddress((void**)&W1t, g_W1t);
    cudaGetSymbolAddress((void**)&W2t, g_W2t);
    cudaGetSymbolAddress((void**)&R1tT, g_R1tT);
    cudaGetSymbolAddress((void**)&R1bT, g_R1bT);
    cudaGetSymbolAddress((void**)&R2t, g_R2t);
    cudaGetSymbolAddress((void**)&sf1, g_sf1);
    cudaGetSymbolAddress((void**)&sf,  g_sf);
    cudaGetSymbolAddress((void**)&qf1, g_qf1);
    cudaGetSymbolAddress((void**)&qf,  g_qf);
    cudaGetSymbolAddress((void**)&protosb, g_protosb);
    cudaGetSymbolAddress((void**)&qp, g_qp);
    cudaGetSymbolAddress((void**)&pp, g_pp);

    const int GEMM_SMEM = 2 * 2 * 128 * 72 * 2;                    // 73728 B
    const int REL_SMEM  = (128 * 520 + 2 * 128 * 72) * 2 + 128 * 4 * 4;  // 172032 B
    cudaFuncSetAttribute(gemm_k<true,  true,  false>, cudaFuncAttributeMaxDynamicSharedMemorySize, GEMM_SMEM);
    cudaFuncSetAttribute(gemm_k<true,  true,  true >, cudaFuncAttributeMaxDynamicSharedMemorySize, GEMM_SMEM);
    cudaFuncSetAttribute(gemm_k<true,  false, true >, cudaFuncAttributeMaxDynamicSharedMemorySize, GEMM_SMEM);
    cudaFuncSetAttribute(gemm_k<false, false, true >, cudaFuncAttributeMaxDynamicSharedMemorySize, GEMM_SMEM);
    cudaFuncSetAttribute(relation_k, cudaFuncAttributeMaxDynamicSharedMemorySize, REL_SMEM);

    // 1) input conversions
    convert_bf16_k<<<(S_N * D_IN / 4 + 255) / 256, 256>>>(support_x, sxb, S_N * D_IN);
    convert_bf16_k<<<(Q_N * D_IN / 4 + 255) / 256, 256>>>(query_x,   qxb, Q_N * D_IN);

    // 2) weight transposes (k-major bf16)
    transpose_convert_k<<<(D_IN * HID + 255) / 256, 256>>>(W1,  W1t,  D_IN, 0);
    transpose_convert_k<<<(HID * HID + 255) / 256, 256>>>(W2,  W2t,  HID, 0);
    transpose_convert_k<<<(HID * HID + 255) / 256, 256>>>(R1w, R1tT, HID, 0);
    transpose_convert_k<<<(HID * HID + 255) / 256, 256>>>(R1w, R1bT, HID, HID);
    transpose_convert_k<<<(HID * HID + 255) / 256, 256>>>(R2w, R2t,  HID, 0);

    // 3) encoders
    gemm_k<true, true, false><<<dim3(4, S_N / 128), 256, GEMM_SMEM>>>(sxb, W1t, b1, nullptr, sf1, S_N, D_IN);
    gemm_k<true, true, false><<<dim3(4, Q_N / 128), 256, GEMM_SMEM>>>(qxb, W1t, b1, nullptr, qf1, Q_N, D_IN);
    gemm_k<true, true, true ><<<dim3(4, S_N / 128), 256, GEMM_SMEM>>>(sf1, W2t, b2, sf, nullptr, S_N, HID);
    gemm_k<true, true, false><<<dim3(4, Q_N / 128), 256, GEMM_SMEM>>>(qf1, W2t, b2, nullptr, qf, Q_N, HID);

    // 4) prototypes
    protos_k<<<WAYS, HID>>>(sf, support_y, protosb);

    // 5) relation first-layer halves
    gemm_k<true,  false, true><<<dim3(4, 1),         256, GEMM_SMEM>>>(protosb, R1bT, R1b, pp, nullptr, WAYS, HID);
    gemm_k<false, false, true><<<dim3(4, Q_N / 128), 256, GEMM_SMEM>>>(qf,      R1tT, nullptr, qp, nullptr, Q_N, HID);

    // 6) fused relation GEMM + R3 reduction + sigmoid
    relation_k<<<Q_N * WAYS / 128, 256, REL_SMEM>>>(qp, pp, R2t, R2b, R3w, R3b, out);
}